// round 1
// baseline (speedup 1.0000x reference)
#include <cuda_runtime.h>

#define N_NODES 40000
#define N_EDGES 640000
#define D 128

// Scratch (device globals -- no allocation allowed in kernel_launch)
__device__ float g_h[(size_t)N_NODES * D];      // intermediate layer activations
__device__ float g_agg[(size_t)N_NODES * D];    // aggregated neighbor features
__device__ int   g_deg[N_NODES];
__device__ float g_inv[N_NODES];
__device__ int   g_rowoff[N_NODES + 1];
__device__ int   g_cursor[N_NODES];
__device__ int   g_csr[N_EDGES];

// ---------------------------------------------------------------------------
// CSR construction
// ---------------------------------------------------------------------------
__global__ void zero_deg_kernel() {
    int i = blockIdx.x * blockDim.x + threadIdx.x;
    if (i < N_NODES) g_deg[i] = 0;
}

__global__ void count_kernel(const int* __restrict__ dst) {
    int e = blockIdx.x * blockDim.x + threadIdx.x;
    if (e < N_EDGES) atomicAdd(&g_deg[dst[e]], 1);
}

// Single-block exclusive scan over 40000 degrees (1024 threads x 40 chunk).
__global__ void scan_kernel() {
    __shared__ int part[1024];
    const int CH = 40;  // 1024*40 = 40960 >= 40000
    int t = threadIdx.x;
    int start = t * CH;
    int s = 0;
    for (int i = 0; i < CH; i++) {
        int idx = start + i;
        if (idx < N_NODES) s += g_deg[idx];
    }
    part[t] = s;
    __syncthreads();
    for (int off = 1; off < 1024; off <<= 1) {
        int v = (t >= off) ? part[t - off] : 0;
        __syncthreads();
        part[t] += v;
        __syncthreads();
    }
    int run = (t == 0) ? 0 : part[t - 1];
    for (int i = 0; i < CH; i++) {
        int idx = start + i;
        if (idx < N_NODES) {
            int d = g_deg[idx];
            g_rowoff[idx] = run;
            g_cursor[idx] = run;
            g_inv[idx] = (d > 0) ? 1.0f / (float)d : 1.0f;
            run += d;
        }
    }
    if (t == 1023) g_rowoff[N_NODES] = part[1023];
}

__global__ void fill_kernel(const int* __restrict__ src, const int* __restrict__ dst) {
    int e = blockIdx.x * blockDim.x + threadIdx.x;
    if (e < N_EDGES) {
        int p = atomicAdd(&g_cursor[dst[e]], 1);
        g_csr[p] = src[e];
    }
}

// ---------------------------------------------------------------------------
// Aggregation: one warp per dst node. Each lane owns 4 consecutive floats
// (float4). Neighbor rows stream from L2 (h fits in 126MB L2). Unroll x2 for MLP.
// ---------------------------------------------------------------------------
__global__ void __launch_bounds__(256) agg_kernel(const float* __restrict__ h) {
    int warp = (blockIdx.x * blockDim.x + threadIdx.x) >> 5;
    int lane = threadIdx.x & 31;
    if (warp >= N_NODES) return;
    int beg = g_rowoff[warp];
    int end = g_rowoff[warp + 1];
    const float4* __restrict__ h4 = (const float4*)h;

    float4 acc = make_float4(0.f, 0.f, 0.f, 0.f);
    int i = beg;
    for (; i + 2 <= end; i += 2) {
        int s0 = g_csr[i];
        int s1 = g_csr[i + 1];
        float4 v0 = h4[s0 * 32 + lane];
        float4 v1 = h4[s1 * 32 + lane];
        acc.x += v0.x; acc.y += v0.y; acc.z += v0.z; acc.w += v0.w;
        acc.x += v1.x; acc.y += v1.y; acc.z += v1.z; acc.w += v1.w;
    }
    if (i < end) {
        int s0 = g_csr[i];
        float4 v0 = h4[s0 * 32 + lane];
        acc.x += v0.x; acc.y += v0.y; acc.z += v0.z; acc.w += v0.w;
    }
    float inv = g_inv[warp];
    acc.x *= inv; acc.y *= inv; acc.z *= inv; acc.w *= inv;
    ((float4*)g_agg)[warp * 32 + lane] = acc;
}

// ---------------------------------------------------------------------------
// Fused GEMM: out = h @ ws + g_agg @ wn + b, optional ReLU.
// Block = 128 threads, processes 64 rows x 128 cols. Both 128x128 weight
// matrices fully resident in SMEM (128KB) + 64-row tiles of h and agg (64KB).
// Thread tile 8 rows x 8 cols => 128 FMA per k-step per thread.
// ---------------------------------------------------------------------------
__global__ void __launch_bounds__(128) gemm_kernel(
    const float* __restrict__ h,
    const float* __restrict__ wsg,
    const float* __restrict__ wng,
    const float* __restrict__ bg,
    float* __restrict__ out,
    int do_relu)
{
    extern __shared__ float sm[];
    float4* ws4 = (float4*)sm;                 // 128x128 fp32 = 4096 float4
    float4* wn4 = (float4*)(sm + 16384);       // 4096 float4
    float*  hs  = sm + 32768;                  // 64x128
    float*  as_ = sm + 40960;                  // 64x128

    int t = threadIdx.x;

    // Stage weights
    const float4* wsg4 = (const float4*)wsg;
    const float4* wng4 = (const float4*)wng;
    #pragma unroll 4
    for (int i = t; i < 4096; i += 128) ws4[i] = wsg4[i];
    #pragma unroll 4
    for (int i = t; i < 4096; i += 128) wn4[i] = wng4[i];

    // Stage 64 rows of h and agg (grid is exactly 625 = 40000/64, no guards)
    size_t row0 = (size_t)blockIdx.x * 64;
    const float4* hg = (const float4*)(h + row0 * D);
    const float4* ag = (const float4*)(g_agg + row0 * D);
    float4* hs4 = (float4*)hs;
    float4* as4 = (float4*)as_;
    #pragma unroll 4
    for (int i = t; i < 2048; i += 128) {
        hs4[i] = hg[i];
        as4[i] = ag[i];
    }
    __syncthreads();

    int cx = t & 15;   // 16 column groups of 8
    int ry = t >> 4;   // 8 row groups of 8

    float acc[8][8];
    #pragma unroll
    for (int r = 0; r < 8; r++)
        #pragma unroll
        for (int c = 0; c < 8; c++) acc[r][c] = 0.f;

    for (int k = 0; k < 128; k++) {
        float4 w0 = ws4[k * 32 + cx * 2];
        float4 w1 = ws4[k * 32 + cx * 2 + 1];
        float4 u0 = wn4[k * 32 + cx * 2];
        float4 u1 = wn4[k * 32 + cx * 2 + 1];
        #pragma unroll
        for (int r = 0; r < 8; r++) {
            float hv = hs[(ry * 8 + r) * D + k];
            float av = as_[(ry * 8 + r) * D + k];
            acc[r][0] = fmaf(hv, w0.x, fmaf(av, u0.x, acc[r][0]));
            acc[r][1] = fmaf(hv, w0.y, fmaf(av, u0.y, acc[r][1]));
            acc[r][2] = fmaf(hv, w0.z, fmaf(av, u0.z, acc[r][2]));
            acc[r][3] = fmaf(hv, w0.w, fmaf(av, u0.w, acc[r][3]));
            acc[r][4] = fmaf(hv, w1.x, fmaf(av, u1.x, acc[r][4]));
            acc[r][5] = fmaf(hv, w1.y, fmaf(av, u1.y, acc[r][5]));
            acc[r][6] = fmaf(hv, w1.z, fmaf(av, u1.z, acc[r][6]));
            acc[r][7] = fmaf(hv, w1.w, fmaf(av, u1.w, acc[r][7]));
        }
    }

    float bb[8];
    #pragma unroll
    for (int c = 0; c < 8; c++) bb[c] = bg[cx * 8 + c];

    #pragma unroll
    for (int r = 0; r < 8; r++) {
        size_t row = row0 + ry * 8 + r;
        float4 o0, o1;
        o0.x = acc[r][0] + bb[0]; o0.y = acc[r][1] + bb[1];
        o0.z = acc[r][2] + bb[2]; o0.w = acc[r][3] + bb[3];
        o1.x = acc[r][4] + bb[4]; o1.y = acc[r][5] + bb[5];
        o1.z = acc[r][6] + bb[6]; o1.w = acc[r][7] + bb[7];
        if (do_relu) {
            o0.x = fmaxf(o0.x, 0.f); o0.y = fmaxf(o0.y, 0.f);
            o0.z = fmaxf(o0.z, 0.f); o0.w = fmaxf(o0.w, 0.f);
            o1.x = fmaxf(o1.x, 0.f); o1.y = fmaxf(o1.y, 0.f);
            o1.z = fmaxf(o1.z, 0.f); o1.w = fmaxf(o1.w, 0.f);
        }
        float4* op = (float4*)(out + row * D + cx * 8);
        op[0] = o0;
        op[1] = o1;
    }
}

// ---------------------------------------------------------------------------
// Launch
// ---------------------------------------------------------------------------
extern "C" void kernel_launch(void* const* d_in, const int* in_sizes, int n_in,
                              void* d_out, int out_size) {
    const float* x       = (const float*)d_in[0];
    const int*   src     = (const int*)d_in[1];
    const int*   dst     = (const int*)d_in[2];
    const float* w_self  = (const float*)d_in[3];
    const float* w_neigh = (const float*)d_in[4];
    const float* b       = (const float*)d_in[5];
    float*       out     = (float*)d_out;

    constexpr size_t GEMM_SMEM = (16384 + 16384 + 8192 + 8192) * sizeof(float); // 192KB
    cudaFuncSetAttribute(gemm_kernel, cudaFuncAttributeMaxDynamicSharedMemorySize,
                         (int)GEMM_SMEM);

    void* hptr_v = nullptr;
    cudaGetSymbolAddress(&hptr_v, g_h);
    float* hptr = (float*)hptr_v;

    // CSR build
    zero_deg_kernel<<<(N_NODES + 255) / 256, 256>>>();
    count_kernel<<<N_EDGES / 256, 256>>>(dst);
    scan_kernel<<<1, 1024>>>();
    fill_kernel<<<N_EDGES / 256, 256>>>(src, dst);

    const int AGG_BLOCKS = N_NODES / 8;   // 256 threads = 8 warps/block, 1 warp/node
    const int GEMM_BLOCKS = N_NODES / 64; // 625

    // Layer 0: agg(x) -> gemm -> g_h (ReLU)
    agg_kernel<<<AGG_BLOCKS, 256>>>(x);
    gemm_kernel<<<GEMM_BLOCKS, 128, GEMM_SMEM>>>(x, w_self, w_neigh, b, hptr, 1);

    // Layer 1: agg(g_h) -> gemm -> out (ReLU)
    agg_kernel<<<AGG_BLOCKS, 256>>>(hptr);
    gemm_kernel<<<GEMM_BLOCKS, 128, GEMM_SMEM>>>(hptr, w_self + 16384, w_neigh + 16384,
                                                 b + 128, out, 1);

    // Layer 2: agg(out) -> gemm -> out in-place (row-local, safe), no ReLU
    agg_kernel<<<AGG_BLOCKS, 256>>>(out);
    gemm_kernel<<<GEMM_BLOCKS, 128, GEMM_SMEM>>>(out, w_self + 32768, w_neigh + 32768,
                                                 b + 256, out, 0);
}

// round 3
// speedup vs baseline: 1.8354x; 1.8354x over previous
#include <cuda_runtime.h>
#include <cuda_bf16.h>
#include <cstdint>

#define N_NODES 40000
#define N_EDGES 640000
#define D 128
#define NTILES 313                     // ceil(40000/128)
#define PADROWS (NTILES * 128)         // 40064

// ---------------------------------------------------------------------------
// Device scratch (zero-initialized; padded rows stay 0)
// ---------------------------------------------------------------------------
__device__ float g_h[(size_t)N_NODES * D];
__device__ int   g_deg[N_NODES];
__device__ float g_inv[N_NODES];
__device__ int   g_rowoff[N_NODES + 1];
__device__ int   g_cursor[N_NODES];
__device__ int   g_csr[N_EDGES];
// bf16 split operand images, row-major [PADROWS][128]
__device__ unsigned short g_Ah_hi[(size_t)PADROWS * D];
__device__ unsigned short g_Ah_lo[(size_t)PADROWS * D];
__device__ unsigned short g_Aa_hi[(size_t)PADROWS * D];
__device__ unsigned short g_Aa_lo[(size_t)PADROWS * D];
// weight images: [layer][hi/lo][n=128][kv=256] (kv<128: Ws^T, kv>=128: Wn^T)
__device__ unsigned short g_Bimg[3][2][128][256];

// ---------------------------------------------------------------------------
// Helpers
// ---------------------------------------------------------------------------
__device__ __forceinline__ void split_bf16(float v, unsigned short& h, unsigned short& l) {
    __nv_bfloat16 hb = __float2bfloat16_rn(v);
    float r = v - __bfloat162float(hb);
    __nv_bfloat16 lb = __float2bfloat16_rn(r);
    h = __bfloat16_as_ushort(hb);
    l = __bfloat16_as_ushort(lb);
}

__device__ __forceinline__ void store_split4(unsigned short* hi, unsigned short* lo,
                                             size_t idx, float4 v) {
    unsigned short h0, h1, h2, h3, l0, l1, l2, l3;
    split_bf16(v.x, h0, l0); split_bf16(v.y, h1, l1);
    split_bf16(v.z, h2, l2); split_bf16(v.w, h3, l3);
    *(uint2*)(hi + idx) = make_uint2((uint32_t)h0 | ((uint32_t)h1 << 16),
                                     (uint32_t)h2 | ((uint32_t)h3 << 16));
    *(uint2*)(lo + idx) = make_uint2((uint32_t)l0 | ((uint32_t)l1 << 16),
                                     (uint32_t)l2 | ((uint32_t)l3 << 16));
}

__device__ __forceinline__ void mma16816(float* c, const uint32_t* a, const uint32_t* b) {
    asm volatile(
        "mma.sync.aligned.m16n8k16.row.col.f32.bf16.bf16.f32 "
        "{%0,%1,%2,%3}, {%4,%5,%6,%7}, {%8,%9}, {%0,%1,%2,%3};"
        : "+f"(c[0]), "+f"(c[1]), "+f"(c[2]), "+f"(c[3])
        : "r"(a[0]), "r"(a[1]), "r"(a[2]), "r"(a[3]), "r"(b[0]), "r"(b[1]));
}

// ---------------------------------------------------------------------------
// CSR construction
// ---------------------------------------------------------------------------
__global__ void zero_deg_kernel() {
    int i = blockIdx.x * blockDim.x + threadIdx.x;
    if (i < N_NODES) g_deg[i] = 0;
}

__global__ void count_kernel(const int* __restrict__ dst) {
    int e = blockIdx.x * blockDim.x + threadIdx.x;
    if (e < N_EDGES) atomicAdd(&g_deg[dst[e]], 1);
}

__global__ void scan_kernel() {
    __shared__ int part[1024];
    const int CH = 40;
    int t = threadIdx.x;
    int start = t * CH;
    int s = 0;
    for (int i = 0; i < CH; i++) {
        int idx = start + i;
        if (idx < N_NODES) s += g_deg[idx];
    }
    part[t] = s;
    __syncthreads();
    for (int off = 1; off < 1024; off <<= 1) {
        int v = (t >= off) ? part[t - off] : 0;
        __syncthreads();
        part[t] += v;
        __syncthreads();
    }
    int run = (t == 0) ? 0 : part[t - 1];
    for (int i = 0; i < CH; i++) {
        int idx = start + i;
        if (idx < N_NODES) {
            int d = g_deg[idx];
            g_rowoff[idx] = run;
            g_cursor[idx] = run;
            g_inv[idx] = (d > 0) ? 1.0f / (float)d : 1.0f;
            run += d;
        }
    }
    if (t == 1023) g_rowoff[N_NODES] = part[1023];
}

__global__ void fill_kernel(const int* __restrict__ src, const int* __restrict__ dst) {
    int e = blockIdx.x * blockDim.x + threadIdx.x;
    if (e < N_EDGES) {
        int p = atomicAdd(&g_cursor[dst[e]], 1);
        g_csr[p] = src[e];
    }
}

// ---------------------------------------------------------------------------
// Weight prep: B[n][kv] = (kv<128 ? Ws : Wn)[k][n], split hi/lo, all 3 layers
// ---------------------------------------------------------------------------
__global__ void bprep_kernel(const float* __restrict__ ws, const float* __restrict__ wn) {
    int idx = blockIdx.x * blockDim.x + threadIdx.x;
    if (idx >= 3 * 128 * 256) return;
    int l = idx >> 15;
    int rem = idx & 32767;
    int n = rem >> 8;
    int kv = rem & 255;
    float v = (kv < 128) ? ws[l * 16384 + kv * 128 + n]
                         : wn[l * 16384 + (kv - 128) * 128 + n];
    unsigned short h, lo;
    split_bf16(v, h, lo);
    g_Bimg[l][0][n][kv] = h;
    g_Bimg[l][1][n][kv] = lo;
}

// ---------------------------------------------------------------------------
// Convert x -> self split images (layer 0)
// ---------------------------------------------------------------------------
__global__ void __launch_bounds__(256) convert_x_kernel(const float* __restrict__ x) {
    int node = (blockIdx.x * blockDim.x + threadIdx.x) >> 5;
    int lane = threadIdx.x & 31;
    if (node >= N_NODES) return;
    float4 v = ((const float4*)x)[node * 32 + lane];
    store_split4(g_Ah_hi, g_Ah_lo, (size_t)node * D + lane * 4, v);
}

// ---------------------------------------------------------------------------
// Aggregation: one warp per dst node; fp32 gather-sum from L2; write split imgs
// ---------------------------------------------------------------------------
__global__ void __launch_bounds__(256) agg_kernel(const float* __restrict__ h) {
    int node = (blockIdx.x * blockDim.x + threadIdx.x) >> 5;
    int lane = threadIdx.x & 31;
    if (node >= N_NODES) return;
    int beg = g_rowoff[node];
    int end = g_rowoff[node + 1];
    const float4* __restrict__ h4 = (const float4*)h;

    float4 acc = make_float4(0.f, 0.f, 0.f, 0.f);
    int i = beg;
    for (; i + 2 <= end; i += 2) {
        int s0 = g_csr[i];
        int s1 = g_csr[i + 1];
        float4 v0 = h4[s0 * 32 + lane];
        float4 v1 = h4[s1 * 32 + lane];
        acc.x += v0.x + v1.x; acc.y += v0.y + v1.y;
        acc.z += v0.z + v1.z; acc.w += v0.w + v1.w;
    }
    if (i < end) {
        int s0 = g_csr[i];
        float4 v0 = h4[s0 * 32 + lane];
        acc.x += v0.x; acc.y += v0.y; acc.z += v0.z; acc.w += v0.w;
    }
    float inv = g_inv[node];
    acc.x *= inv; acc.y *= inv; acc.z *= inv; acc.w *= inv;
    store_split4(g_Aa_hi, g_Aa_lo, (size_t)node * D + lane * 4, acc);
}

// ---------------------------------------------------------------------------
// mma.sync bf16-split GEMM: out[tile 128x128] = [h|agg] @ [Ws;Wn] + b (+ReLU)
// Virtual K=256, chunked by 32 through SMEM (row pad 80B = conflict-free).
// 8 warps: warp grid 4(M) x 2(N); warp tile 32x64; acc stays in registers
// across both matrices and all 3 split passes.
// ---------------------------------------------------------------------------
#define RP 20   // padded row stride in 4B words (80B = 32 bf16 + 8B pad)

__global__ void __launch_bounds__(256) mma_gemm_kernel(
    int layer, const float* __restrict__ bias, float* __restrict__ out,
    int do_relu, int write_img)
{
    __shared__ __align__(16) uint32_t sA[2][128 * RP];
    __shared__ __align__(16) uint32_t sB[2][128 * RP];
    __shared__ float sbias[128];

    int tid = threadIdx.x;
    int wid = tid >> 5, lane = tid & 31;
    int wm = wid >> 1;        // 0..3 -> m base = wm*32
    int wn = wid & 1;         // 0..1 -> n base = wn*64
    int g = lane >> 2;        // 0..7
    int c = lane & 3;         // 0..3
    int tile = blockIdx.x;
    size_t row0 = (size_t)tile * 128;

    if (tid < 128) sbias[tid] = bias[tid];

    float acc[2][8][4];
    #pragma unroll
    for (int mf = 0; mf < 2; mf++)
        #pragma unroll
        for (int nf = 0; nf < 8; nf++)
            #pragma unroll
            for (int k = 0; k < 4; k++) acc[mf][nf][k] = 0.f;

    for (int ch = 0; ch < 8; ch++) {
        __syncthreads();   // previous chunk fully consumed
        // --- stage A chunk: 128 rows x 32 kv, hi+lo ---
        {
            const unsigned short* hi = (ch < 4) ? g_Ah_hi : g_Aa_hi;
            const unsigned short* lo = (ch < 4) ? g_Ah_lo : g_Aa_lo;
            int kc = (ch & 3) * 32;
            #pragma unroll
            for (int it = 0; it < 4; it++) {
                int i = tid + it * 256;           // 0..1023
                int img = i >> 9;                 // 0..1
                int r = (i >> 2) & 127;
                int seg = i & 3;
                const unsigned short* srcp = (img ? lo : hi) + (row0 + r) * D + kc + seg * 8;
                ((uint4*)&sA[img][r * RP])[seg] = *(const uint4*)srcp;
            }
        }
        // --- stage B chunk: 128 n x 32 kv, hi+lo ---
        {
            #pragma unroll
            for (int it = 0; it < 4; it++) {
                int i = tid + it * 256;
                int img = i >> 9;
                int n = (i >> 2) & 127;
                int seg = i & 3;
                const unsigned short* srcp = &g_Bimg[layer][img][n][ch * 32 + seg * 8];
                ((uint4*)&sB[img][n * RP])[seg] = *(const uint4*)srcp;
            }
        }
        __syncthreads();

        // --- compute: 2 k16 steps, 3 split passes each ---
        #pragma unroll
        for (int kk = 0; kk < 2; kk++) {
            uint32_t ah[2][4], al[2][4], bh[8][2], bl[8][2];
            #pragma unroll
            for (int mf = 0; mf < 2; mf++) {
                int wb = (wm * 32 + mf * 16 + g) * RP + kk * 8 + c;
                ah[mf][0] = sA[0][wb];
                ah[mf][1] = sA[0][wb + 8 * RP];
                ah[mf][2] = sA[0][wb + 4];
                ah[mf][3] = sA[0][wb + 8 * RP + 4];
                al[mf][0] = sA[1][wb];
                al[mf][1] = sA[1][wb + 8 * RP];
                al[mf][2] = sA[1][wb + 4];
                al[mf][3] = sA[1][wb + 8 * RP + 4];
            }
            #pragma unroll
            for (int nf = 0; nf < 8; nf++) {
                int wb = (wn * 64 + nf * 8 + g) * RP + kk * 8 + c;
                bh[nf][0] = sB[0][wb];
                bh[nf][1] = sB[0][wb + 4];
                bl[nf][0] = sB[1][wb];
                bl[nf][1] = sB[1][wb + 4];
            }
            #pragma unroll
            for (int mf = 0; mf < 2; mf++)
                #pragma unroll
                for (int nf = 0; nf < 8; nf++) {
                    mma16816(acc[mf][nf], ah[mf], bh[nf]);
                    mma16816(acc[mf][nf], ah[mf], bl[nf]);
                    mma16816(acc[mf][nf], al[mf], bh[nf]);
                }
        }
    }

    // --- epilogue: bias + relu, write fp32 out (+ next-layer self images) ---
    #pragma unroll
    for (int mf = 0; mf < 2; mf++) {
        size_t r_lo = row0 + wm * 32 + mf * 16 + g;
        size_t r_hi = r_lo + 8;
        #pragma unroll
        for (int nf = 0; nf < 8; nf++) {
            int col = wn * 64 + nf * 8 + c * 2;
            float b0 = sbias[col], b1 = sbias[col + 1];
            float v00 = acc[mf][nf][0] + b0, v01 = acc[mf][nf][1] + b1;
            float v10 = acc[mf][nf][2] + b0, v11 = acc[mf][nf][3] + b1;
            if (do_relu) {
                v00 = fmaxf(v00, 0.f); v01 = fmaxf(v01, 0.f);
                v10 = fmaxf(v10, 0.f); v11 = fmaxf(v11, 0.f);
            }
            if (r_lo < N_NODES) {
                *(float2*)(out + r_lo * D + col) = make_float2(v00, v01);
                if (write_img) {
                    unsigned short h0, h1, l0, l1;
                    split_bf16(v00, h0, l0); split_bf16(v01, h1, l1);
                    *(uint32_t*)(g_Ah_hi + r_lo * D + col) = (uint32_t)h0 | ((uint32_t)h1 << 16);
                    *(uint32_t*)(g_Ah_lo + r_lo * D + col) = (uint32_t)l0 | ((uint32_t)l1 << 16);
                }
            }
            if (r_hi < N_NODES) {
                *(float2*)(out + r_hi * D + col) = make_float2(v10, v11);
                if (write_img) {
                    unsigned short h0, h1, l0, l1;
                    split_bf16(v10, h0, l0); split_bf16(v11, h1, l1);
                    *(uint32_t*)(g_Ah_hi + r_hi * D + col) = (uint32_t)h0 | ((uint32_t)h1 << 16);
                    *(uint32_t*)(g_Ah_lo + r_hi * D + col) = (uint32_t)l0 | ((uint32_t)l1 << 16);
                }
            }
        }
    }
}

// ---------------------------------------------------------------------------
// Launch
// ---------------------------------------------------------------------------
extern "C" void kernel_launch(void* const* d_in, const int* in_sizes, int n_in,
                              void* d_out, int out_size) {
    const float* x       = (const float*)d_in[0];
    const int*   src     = (const int*)d_in[1];
    const int*   dst     = (const int*)d_in[2];
    const float* w_self  = (const float*)d_in[3];
    const float* w_neigh = (const float*)d_in[4];
    const float* b       = (const float*)d_in[5];
    float*       out     = (float*)d_out;

    void* hptr_v = nullptr;
    cudaGetSymbolAddress(&hptr_v, g_h);
    float* hptr = (float*)hptr_v;

    // Prep: weight images, CSR, x conversion
    bprep_kernel<<<384, 256>>>(w_self, w_neigh);
    zero_deg_kernel<<<(N_NODES + 255) / 256, 256>>>();
    count_kernel<<<N_EDGES / 256, 256>>>(dst);
    scan_kernel<<<1, 1024>>>();
    fill_kernel<<<N_EDGES / 256, 256>>>(src, dst);
    convert_x_kernel<<<N_NODES / 8, 256>>>(x);

    // Layer 0: agg(x); gemm -> g_h (fp32) + self images for layer 1
    agg_kernel<<<N_NODES / 8, 256>>>(x);
    mma_gemm_kernel<<<NTILES, 256>>>(0, b, hptr, 1, 1);
    // Layer 1: agg(g_h); gemm -> g_h + self images for layer 2
    agg_kernel<<<N_NODES / 8, 256>>>(hptr);
    mma_gemm_kernel<<<NTILES, 256>>>(1, b + 128, hptr, 1, 1);
    // Layer 2: agg(g_h); gemm -> out (no relu, no images)
    agg_kernel<<<N_NODES / 8, 256>>>(hptr);
    mma_gemm_kernel<<<NTILES, 256>>>(2, b + 256, out, 0, 0);
}

// round 4
// speedup vs baseline: 2.3916x; 1.3031x over previous
#include <cuda_runtime.h>
#include <cuda_bf16.h>
#include <cstdint>

#define N_NODES 40000
#define N_EDGES 640000
#define D 128
#define NTILES 313                     // ceil(40000/128)
#define PADROWS (NTILES * 128)         // 40064

// ---------------------------------------------------------------------------
// Device scratch (zero-initialized; padded rows stay 0)
// ---------------------------------------------------------------------------
__device__ float g_h[(size_t)N_NODES * D];
__device__ int   g_deg[N_NODES];
__device__ float g_inv[N_NODES];
__device__ int   g_rowoff[N_NODES];
__device__ int   g_cursor[N_NODES];
__device__ int   g_total;
__device__ int   g_csr[N_EDGES];
// bf16 split operand images, row-major [PADROWS][128]
__device__ unsigned short g_Ah_hi[(size_t)PADROWS * D];
__device__ unsigned short g_Ah_lo[(size_t)PADROWS * D];
__device__ unsigned short g_Aa_hi[(size_t)PADROWS * D];
__device__ unsigned short g_Aa_lo[(size_t)PADROWS * D];
// weight images: [layer][hi/lo][n=128][kv=256] (kv<128: Ws^T, kv>=128: Wn^T)
__device__ unsigned short g_Bimg[3][2][128][256];

// ---------------------------------------------------------------------------
// Helpers
// ---------------------------------------------------------------------------
__device__ __forceinline__ void split_bf16(float v, unsigned short& h, unsigned short& l) {
    __nv_bfloat16 hb = __float2bfloat16_rn(v);
    float r = v - __bfloat162float(hb);
    __nv_bfloat16 lb = __float2bfloat16_rn(r);
    h = __bfloat16_as_ushort(hb);
    l = __bfloat16_as_ushort(lb);
}

__device__ __forceinline__ void store_split4(unsigned short* hi, unsigned short* lo,
                                             size_t idx, float4 v) {
    unsigned short h0, h1, h2, h3, l0, l1, l2, l3;
    split_bf16(v.x, h0, l0); split_bf16(v.y, h1, l1);
    split_bf16(v.z, h2, l2); split_bf16(v.w, h3, l3);
    *(uint2*)(hi + idx) = make_uint2((uint32_t)h0 | ((uint32_t)h1 << 16),
                                     (uint32_t)h2 | ((uint32_t)h3 << 16));
    *(uint2*)(lo + idx) = make_uint2((uint32_t)l0 | ((uint32_t)l1 << 16),
                                     (uint32_t)l2 | ((uint32_t)l3 << 16));
}

__device__ __forceinline__ void mma16816(float* c, const uint32_t* a, const uint32_t* b) {
    asm volatile(
        "mma.sync.aligned.m16n8k16.row.col.f32.bf16.bf16.f32 "
        "{%0,%1,%2,%3}, {%4,%5,%6,%7}, {%8,%9}, {%0,%1,%2,%3};"
        : "+f"(c[0]), "+f"(c[1]), "+f"(c[2]), "+f"(c[3])
        : "r"(a[0]), "r"(a[1]), "r"(a[2]), "r"(a[3]), "r"(b[0]), "r"(b[1]));
}

__device__ __forceinline__ uint32_t smem_u32(const void* p) {
    uint32_t a;
    asm("{ .reg .u64 t; cvta.to.shared.u64 t, %1; cvt.u32.u64 %0, t; }" : "=r"(a) : "l"(p));
    return a;
}

__device__ __forceinline__ void cp16(uint32_t s, const void* g) {
    asm volatile("cp.async.cg.shared.global [%0], [%1], 16;" :: "r"(s), "l"(g));
}
#define CP_COMMIT() asm volatile("cp.async.commit_group;" ::: "memory")
#define CP_WAIT(n)  asm volatile("cp.async.wait_group %0;" :: "n"(n) : "memory")

// ---------------------------------------------------------------------------
// CSR construction (no prefix scan: segment starts via atomic counter)
// ---------------------------------------------------------------------------
__global__ void zero_deg_kernel() {
    int i = blockIdx.x * blockDim.x + threadIdx.x;
    if (i < N_NODES) g_deg[i] = 0;
    if (i == 0) g_total = 0;
}

__global__ void count_kernel(const int* __restrict__ dst) {
    int e = blockIdx.x * blockDim.x + threadIdx.x;
    if (e < N_EDGES) atomicAdd(&g_deg[dst[e]], 1);
}

__global__ void offsets_kernel() {
    int i = blockIdx.x * blockDim.x + threadIdx.x;
    if (i < N_NODES) {
        int d = g_deg[i];
        int off = (d > 0) ? atomicAdd(&g_total, d) : 0;
        g_rowoff[i] = off;
        g_cursor[i] = off;
        g_inv[i] = (d > 0) ? 1.0f / (float)d : 1.0f;
    }
}

__global__ void fill_kernel(const int* __restrict__ src, const int* __restrict__ dst) {
    int e = blockIdx.x * blockDim.x + threadIdx.x;
    if (e < N_EDGES) {
        int p = atomicAdd(&g_cursor[dst[e]], 1);
        g_csr[p] = src[e];
    }
}

// ---------------------------------------------------------------------------
// Weight prep: B[n][kv] = (kv<128 ? Ws : Wn)[k][n], split hi/lo, all 3 layers
// ---------------------------------------------------------------------------
__global__ void bprep_kernel(const float* __restrict__ ws, const float* __restrict__ wn) {
    int idx = blockIdx.x * blockDim.x + threadIdx.x;
    if (idx >= 3 * 128 * 256) return;
    int l = idx >> 15;
    int rem = idx & 32767;
    int n = rem >> 8;
    int kv = rem & 255;
    float v = (kv < 128) ? ws[l * 16384 + kv * 128 + n]
                         : wn[l * 16384 + (kv - 128) * 128 + n];
    unsigned short h, lo;
    split_bf16(v, h, lo);
    g_Bimg[l][0][n][kv] = h;
    g_Bimg[l][1][n][kv] = lo;
}

// ---------------------------------------------------------------------------
// Aggregation: one warp per dst node; fp32 gather-sum from L2; write split
// images. write_self=1 also converts this node's own row (layer-0 x path).
// ---------------------------------------------------------------------------
__global__ void __launch_bounds__(256) agg_kernel(const float* __restrict__ h,
                                                  int write_self) {
    int node = (blockIdx.x * blockDim.x + threadIdx.x) >> 5;
    int lane = threadIdx.x & 31;
    if (node >= N_NODES) return;
    int beg = g_rowoff[node];
    int end = beg + g_deg[node];
    const float4* __restrict__ h4 = (const float4*)h;

    if (write_self) {
        float4 self = h4[node * 32 + lane];
        store_split4(g_Ah_hi, g_Ah_lo, (size_t)node * D + lane * 4, self);
    }

    float4 acc = make_float4(0.f, 0.f, 0.f, 0.f);
    int i = beg;
    for (; i + 2 <= end; i += 2) {
        int s0 = g_csr[i];
        int s1 = g_csr[i + 1];
        float4 v0 = h4[s0 * 32 + lane];
        float4 v1 = h4[s1 * 32 + lane];
        acc.x += v0.x + v1.x; acc.y += v0.y + v1.y;
        acc.z += v0.z + v1.z; acc.w += v0.w + v1.w;
    }
    if (i < end) {
        int s0 = g_csr[i];
        float4 v0 = h4[s0 * 32 + lane];
        acc.x += v0.x; acc.y += v0.y; acc.z += v0.z; acc.w += v0.w;
    }
    float inv = g_inv[node];
    acc.x *= inv; acc.y *= inv; acc.z *= inv; acc.w *= inv;
    store_split4(g_Aa_hi, g_Aa_lo, (size_t)node * D + lane * 4, acc);
}

// ---------------------------------------------------------------------------
// mma.sync bf16-split GEMM, double-buffered via cp.async.
// out[tile 128x128] = [h|agg] @ [Ws;Wn] + b (+ReLU). Virtual K=256 in 8
// chunks of 32 (row pad 80B = conflict-free). 8 warps: 4(M) x 2(N),
// warp tile 32x64, acc in registers across all chunks / split passes.
// ---------------------------------------------------------------------------
#define RP 20                       // padded row stride in 4B words (80B)
#define IMG_WORDS (128 * RP)        // 2560 u32 = 10240 B
#define BUF_WORDS (2 * IMG_WORDS)   // hi+lo images, one chunk
// dynamic smem: sA[2 buf][2 img][2560] | sB[2 buf][2 img][2560] | bias[128]
#define SM_A(buf) (0 + (buf) * BUF_WORDS)
#define SM_B(buf) (4 * IMG_WORDS + (buf) * BUF_WORDS)
#define SM_BIAS   (8 * IMG_WORDS)
#define SMEM_WORDS (8 * IMG_WORDS + 128)

__global__ void __launch_bounds__(256) mma_gemm_kernel(
    int layer, const float* __restrict__ bias, float* __restrict__ out,
    int do_relu, int write_img)
{
    extern __shared__ __align__(16) uint32_t sm[];
    uint32_t smb = smem_u32(sm);

    int tid = threadIdx.x;
    int wid = tid >> 5, lane = tid & 31;
    int wm = wid >> 1;        // m base = wm*32
    int wn = wid & 1;         // n base = wn*64
    int g = lane >> 2;        // 0..7
    int c = lane & 3;         // 0..3
    int tile = blockIdx.x;
    size_t row0 = (size_t)tile * 128;

    if (tid < 128) sm[SM_BIAS + tid] = __float_as_uint(bias[tid]);

    // staging decomposition: 4 A-vecs + 4 B-vecs per thread per chunk
    int s_img = tid >> 7;            // 0..1
    int s_r   = (tid >> 1) & 63;     // reused twice (r and r+64)
    int s_seg = tid & 1;             // 2 segs of 16B x2 per iteration

    float acc[2][8][4];
    #pragma unroll
    for (int mf = 0; mf < 2; mf++)
        #pragma unroll
        for (int nf = 0; nf < 8; nf++)
            #pragma unroll
            for (int k = 0; k < 4; k++) acc[mf][nf][k] = 0.f;

    // stage one chunk (ch) into buffer buf
    auto stage = [&](int ch, int buf) {
        const unsigned short* Ahi = (ch < 4) ? g_Ah_hi : g_Aa_hi;
        const unsigned short* Alo = (ch < 4) ? g_Ah_lo : g_Aa_lo;
        int kc = (ch & 3) * 32;
        const unsigned short* Aimg = s_img ? Alo : Ahi;
        #pragma unroll
        for (int half = 0; half < 2; half++) {
            int r = s_r + half * 64;
            #pragma unroll
            for (int sg = 0; sg < 2; sg++) {
                int seg = s_seg * 2 + sg;
                cp16(smb + (SM_A(buf) + s_img * IMG_WORDS + r * RP + seg * 4) * 4,
                     Aimg + (row0 + r) * D + kc + seg * 8);
                cp16(smb + (SM_B(buf) + s_img * IMG_WORDS + r * RP + seg * 4) * 4,
                     &g_Bimg[layer][s_img][r][ch * 32 + seg * 8]);
            }
        }
    };

    stage(0, 0);
    CP_COMMIT();

    for (int ch = 0; ch < 8; ch++) {
        int buf = ch & 1;
        if (ch < 7) {
            stage(ch + 1, buf ^ 1);
            CP_COMMIT();
            CP_WAIT(1);
        } else {
            CP_WAIT(0);
        }
        __syncthreads();

        const uint32_t* A0 = sm + SM_A(buf);
        const uint32_t* A1 = sm + SM_A(buf) + IMG_WORDS;
        const uint32_t* B0 = sm + SM_B(buf);
        const uint32_t* B1 = sm + SM_B(buf) + IMG_WORDS;

        #pragma unroll
        for (int kk = 0; kk < 2; kk++) {
            uint32_t ah[2][4], al[2][4], bh[8][2], bl[8][2];
            #pragma unroll
            for (int mf = 0; mf < 2; mf++) {
                int wb = (wm * 32 + mf * 16 + g) * RP + kk * 8 + c;
                ah[mf][0] = A0[wb];
                ah[mf][1] = A0[wb + 8 * RP];
                ah[mf][2] = A0[wb + 4];
                ah[mf][3] = A0[wb + 8 * RP + 4];
                al[mf][0] = A1[wb];
                al[mf][1] = A1[wb + 8 * RP];
                al[mf][2] = A1[wb + 4];
                al[mf][3] = A1[wb + 8 * RP + 4];
            }
            #pragma unroll
            for (int nf = 0; nf < 8; nf++) {
                int wb = (wn * 64 + nf * 8 + g) * RP + kk * 8 + c;
                bh[nf][0] = B0[wb];
                bh[nf][1] = B0[wb + 4];
                bl[nf][0] = B1[wb];
                bl[nf][1] = B1[wb + 4];
            }
            #pragma unroll
            for (int mf = 0; mf < 2; mf++)
                #pragma unroll
                for (int nf = 0; nf < 8; nf++) {
                    mma16816(acc[mf][nf], ah[mf], bh[nf]);
                    mma16816(acc[mf][nf], ah[mf], bl[nf]);
                    mma16816(acc[mf][nf], al[mf], bh[nf]);
                }
        }
        __syncthreads();
    }

    // --- epilogue: bias + relu, write fp32 out (+ next-layer self images) ---
    const float* bias_sm = (const float*)(sm + SM_BIAS);
    #pragma unroll
    for (int mf = 0; mf < 2; mf++) {
        size_t r_lo = row0 + wm * 32 + mf * 16 + g;
        size_t r_hi = r_lo + 8;
        #pragma unroll
        for (int nf = 0; nf < 8; nf++) {
            int col = wn * 64 + nf * 8 + c * 2;
            float b0 = bias_sm[col], b1 = bias_sm[col + 1];
            float v00 = acc[mf][nf][0] + b0, v01 = acc[mf][nf][1] + b1;
            float v10 = acc[mf][nf][2] + b0, v11 = acc[mf][nf][3] + b1;
            if (do_relu) {
                v00 = fmaxf(v00, 0.f); v01 = fmaxf(v01, 0.f);
                v10 = fmaxf(v10, 0.f); v11 = fmaxf(v11, 0.f);
            }
            if (r_lo < N_NODES) {
                *(float2*)(out + r_lo * D + col) = make_float2(v00, v01);
                if (write_img) {
                    unsigned short h0, h1, l0, l1;
                    split_bf16(v00, h0, l0); split_bf16(v01, h1, l1);
                    *(uint32_t*)(g_Ah_hi + r_lo * D + col) = (uint32_t)h0 | ((uint32_t)h1 << 16);
                    *(uint32_t*)(g_Ah_lo + r_lo * D + col) = (uint32_t)l0 | ((uint32_t)l1 << 16);
                }
            }
            if (r_hi < N_NODES) {
                *(float2*)(out + r_hi * D + col) = make_float2(v10, v11);
                if (write_img) {
                    unsigned short h0, h1, l0, l1;
                    split_bf16(v10, h0, l0); split_bf16(v11, h1, l1);
                    *(uint32_t*)(g_Ah_hi + r_hi * D + col) = (uint32_t)h0 | ((uint32_t)h1 << 16);
                    *(uint32_t*)(g_Ah_lo + r_hi * D + col) = (uint32_t)l0 | ((uint32_t)l1 << 16);
                }
            }
        }
    }
}

// ---------------------------------------------------------------------------
// Launch
// ---------------------------------------------------------------------------
extern "C" void kernel_launch(void* const* d_in, const int* in_sizes, int n_in,
                              void* d_out, int out_size) {
    const float* x       = (const float*)d_in[0];
    const int*   src     = (const int*)d_in[1];
    const int*   dst     = (const int*)d_in[2];
    const float* w_self  = (const float*)d_in[3];
    const float* w_neigh = (const float*)d_in[4];
    const float* b       = (const float*)d_in[5];
    float*       out     = (float*)d_out;

    cudaFuncSetAttribute(mma_gemm_kernel, cudaFuncAttributeMaxDynamicSharedMemorySize,
                         SMEM_WORDS * 4);

    void* hptr_v = nullptr;
    cudaGetSymbolAddress(&hptr_v, g_h);
    float* hptr = (float*)hptr_v;

    // Prep: weight images + CSR (scan-free)
    bprep_kernel<<<384, 256>>>(w_self, w_neigh);
    zero_deg_kernel<<<(N_NODES + 255) / 256, 256>>>();
    count_kernel<<<N_EDGES / 256, 256>>>(dst);
    offsets_kernel<<<(N_NODES + 255) / 256, 256>>>();
    fill_kernel<<<N_EDGES / 256, 256>>>(src, dst);

    // Layer 0: agg(x) + convert x self images; gemm -> g_h + self images
    agg_kernel<<<N_NODES / 8, 256>>>(x, 1);
    mma_gemm_kernel<<<NTILES, 256, SMEM_WORDS * 4>>>(0, b, hptr, 1, 1);
    // Layer 1
    agg_kernel<<<N_NODES / 8, 256>>>(hptr, 0);
    mma_gemm_kernel<<<NTILES, 256, SMEM_WORDS * 4>>>(1, b + 128, hptr, 1, 1);
    // Layer 2: -> out, no relu, no images
    agg_kernel<<<N_NODES / 8, 256>>>(hptr, 0);
    mma_gemm_kernel<<<NTILES, 256, SMEM_WORDS * 4>>>(2, b + 256, out, 0, 0);
}

// round 5
// speedup vs baseline: 2.7369x; 1.1444x over previous
#include <cuda_runtime.h>
#include <cuda_bf16.h>
#include <cstdint>

#define N_NODES 40000
#define N_EDGES 640000
#define D 128
#define TILE_M 64
#define NTILES 626                     // 40064 / 64
#define PADROWS (NTILES * TILE_M)      // 40064

// ---------------------------------------------------------------------------
// Device scratch (zero-initialized; padded rows stay 0)
// ---------------------------------------------------------------------------
__device__ float g_h[(size_t)N_NODES * D];
__device__ int   g_deg[N_NODES];
__device__ float g_inv[N_NODES];
__device__ int   g_rowoff[N_NODES];
__device__ int   g_cursor[N_NODES];
__device__ int   g_total;
__device__ int   g_csr[N_EDGES];
// bf16 split operand images, row-major [PADROWS][128]
__device__ unsigned short g_Ah_hi[(size_t)PADROWS * D];
__device__ unsigned short g_Ah_lo[(size_t)PADROWS * D];
__device__ unsigned short g_Aa_hi[(size_t)PADROWS * D];
__device__ unsigned short g_Aa_lo[(size_t)PADROWS * D];
// weight images: [layer][hi/lo][n=128][kv=256] (kv<128: Ws^T, kv>=128: Wn^T)
__device__ unsigned short g_Bimg[3][2][128][256];

// ---------------------------------------------------------------------------
// Helpers
// ---------------------------------------------------------------------------
__device__ __forceinline__ void split_bf16(float v, unsigned short& h, unsigned short& l) {
    __nv_bfloat16 hb = __float2bfloat16_rn(v);
    float r = v - __bfloat162float(hb);
    __nv_bfloat16 lb = __float2bfloat16_rn(r);
    h = __bfloat16_as_ushort(hb);
    l = __bfloat16_as_ushort(lb);
}

__device__ __forceinline__ void store_split4(unsigned short* hi, unsigned short* lo,
                                             size_t idx, float4 v) {
    unsigned short h0, h1, h2, h3, l0, l1, l2, l3;
    split_bf16(v.x, h0, l0); split_bf16(v.y, h1, l1);
    split_bf16(v.z, h2, l2); split_bf16(v.w, h3, l3);
    *(uint2*)(hi + idx) = make_uint2((uint32_t)h0 | ((uint32_t)h1 << 16),
                                     (uint32_t)h2 | ((uint32_t)h3 << 16));
    *(uint2*)(lo + idx) = make_uint2((uint32_t)l0 | ((uint32_t)l1 << 16),
                                     (uint32_t)l2 | ((uint32_t)l3 << 16));
}

__device__ __forceinline__ void mma16816(float* c, const uint32_t* a, const uint32_t* b) {
    asm volatile(
        "mma.sync.aligned.m16n8k16.row.col.f32.bf16.bf16.f32 "
        "{%0,%1,%2,%3}, {%4,%5,%6,%7}, {%8,%9}, {%0,%1,%2,%3};"
        : "+f"(c[0]), "+f"(c[1]), "+f"(c[2]), "+f"(c[3])
        : "r"(a[0]), "r"(a[1]), "r"(a[2]), "r"(a[3]), "r"(b[0]), "r"(b[1]));
}

__device__ __forceinline__ uint32_t smem_u32(const void* p) {
    uint32_t a;
    asm("{ .reg .u64 t; cvta.to.shared.u64 t, %1; cvt.u32.u64 %0, t; }" : "=r"(a) : "l"(p));
    return a;
}

__device__ __forceinline__ void cp16(uint32_t s, const void* g) {
    asm volatile("cp.async.cg.shared.global [%0], [%1], 16;" :: "r"(s), "l"(g));
}
#define CP_COMMIT() asm volatile("cp.async.commit_group;" ::: "memory")
#define CP_WAIT(n)  asm volatile("cp.async.wait_group %0;" :: "n"(n) : "memory")

// ---------------------------------------------------------------------------
// CSR construction (scan-free: segment starts via atomic counter)
// ---------------------------------------------------------------------------
__global__ void bprep_zero_kernel(const float* __restrict__ ws,
                                  const float* __restrict__ wn) {
    int idx = blockIdx.x * blockDim.x + threadIdx.x;
    if (idx < N_NODES) g_deg[idx] = 0;
    if (idx == 0) g_total = 0;
    if (idx >= 3 * 128 * 256) return;
    int l = idx >> 15;
    int rem = idx & 32767;
    int n = rem >> 8;
    int kv = rem & 255;
    float v = (kv < 128) ? ws[l * 16384 + kv * 128 + n]
                         : wn[l * 16384 + (kv - 128) * 128 + n];
    unsigned short h, lo;
    split_bf16(v, h, lo);
    g_Bimg[l][0][n][kv] = h;
    g_Bimg[l][1][n][kv] = lo;
}

__global__ void count_kernel(const int* __restrict__ dst) {
    int e = blockIdx.x * blockDim.x + threadIdx.x;
    if (e < N_EDGES) atomicAdd(&g_deg[dst[e]], 1);
}

__global__ void offsets_kernel() {
    int i = blockIdx.x * blockDim.x + threadIdx.x;
    if (i < N_NODES) {
        int d = g_deg[i];
        int off = (d > 0) ? atomicAdd(&g_total, d) : 0;
        g_rowoff[i] = off;
        g_cursor[i] = off;
        g_inv[i] = (d > 0) ? 1.0f / (float)d : 1.0f;
    }
}

__global__ void fill_kernel(const int* __restrict__ src, const int* __restrict__ dst) {
    int e = blockIdx.x * blockDim.x + threadIdx.x;
    if (e < N_EDGES) {
        int p = atomicAdd(&g_cursor[dst[e]], 1);
        g_csr[p] = src[e];
    }
}

// ---------------------------------------------------------------------------
// Aggregation: one warp per dst node; fp32 gather-sum from L2 (4-deep MLP);
// writes split bf16 images. write_self=1 also converts own row (layer 0).
// ---------------------------------------------------------------------------
__global__ void __launch_bounds__(256) agg_kernel(const float* __restrict__ h,
                                                  int write_self) {
    int node = (blockIdx.x * blockDim.x + threadIdx.x) >> 5;
    int lane = threadIdx.x & 31;
    if (node >= N_NODES) return;
    int beg = g_rowoff[node];
    int end = beg + g_deg[node];
    const float4* __restrict__ h4 = (const float4*)h;

    if (write_self) {
        float4 self = h4[node * 32 + lane];
        store_split4(g_Ah_hi, g_Ah_lo, (size_t)node * D + lane * 4, self);
    }

    float4 acc = make_float4(0.f, 0.f, 0.f, 0.f);
    int i = beg;
    for (; i + 4 <= end; i += 4) {
        int s0 = g_csr[i], s1 = g_csr[i + 1], s2 = g_csr[i + 2], s3 = g_csr[i + 3];
        float4 v0 = h4[s0 * 32 + lane];
        float4 v1 = h4[s1 * 32 + lane];
        float4 v2 = h4[s2 * 32 + lane];
        float4 v3 = h4[s3 * 32 + lane];
        acc.x += (v0.x + v1.x) + (v2.x + v3.x);
        acc.y += (v0.y + v1.y) + (v2.y + v3.y);
        acc.z += (v0.z + v1.z) + (v2.z + v3.z);
        acc.w += (v0.w + v1.w) + (v2.w + v3.w);
    }
    for (; i < end; i++) {
        int s0 = g_csr[i];
        float4 v0 = h4[s0 * 32 + lane];
        acc.x += v0.x; acc.y += v0.y; acc.z += v0.z; acc.w += v0.w;
    }
    float inv = g_inv[node];
    acc.x *= inv; acc.y *= inv; acc.z *= inv; acc.w *= inv;
    store_split4(g_Aa_hi, g_Aa_lo, (size_t)node * D + lane * 4, acc);
}

// ---------------------------------------------------------------------------
// mma.sync bf16-split GEMM, M=64 tiles (626 CTAs), A fully SMEM-resident,
// B double-buffered via cp.async in 8 k-chunks of 32.
// out[64x128] = [h|agg] @ [Ws;Wn] + b (+ReLU).
// 8 warps: 2(M) x 4(N); warp tile 32x32.
// ---------------------------------------------------------------------------
#define RPA 68                          // A row stride (words): 64 data + 4 pad
#define RPB 20                          // B row stride (words): 16 data + 4 pad
#define A_IMG (64 * RPA)                // 4352 words per image
#define OFF_AS 0                        // self hi, lo at +A_IMG
#define OFF_AA (2 * A_IMG)              // agg hi, lo at +A_IMG
#define B_IMG (128 * RPB)               // 2560 words per image
#define OFF_B  (4 * A_IMG)              // [buf][img]: + buf*2*B_IMG + img*B_IMG
#define OFF_BIAS (4 * A_IMG + 4 * B_IMG)
#define SMEM_WORDS (OFF_BIAS + 128)     // 27776 words = 111104 B

__global__ void __launch_bounds__(256) mma_gemm_kernel(
    int layer, const float* __restrict__ bias, float* __restrict__ out,
    int do_relu, int write_img)
{
    extern __shared__ __align__(16) uint32_t sm[];
    uint32_t smb = smem_u32(sm);

    int tid = threadIdx.x;
    int wid = tid >> 5, lane = tid & 31;
    int wm = wid >> 2;        // 0..1 -> m base = wm*32
    int wn = wid & 3;         // 0..3 -> n base = wn*32
    int g = lane >> 2;        // 0..7
    int c = lane & 3;         // 0..3
    size_t row0 = (size_t)blockIdx.x * TILE_M;

    if (tid < 128) sm[OFF_BIAS + tid] = __float_as_uint(bias[tid]);

    float acc[2][4][4];
    #pragma unroll
    for (int mf = 0; mf < 2; mf++)
        #pragma unroll
        for (int nf = 0; nf < 4; nf++)
            #pragma unroll
            for (int k = 0; k < 4; k++) acc[mf][nf][k] = 0.f;

    // --- stage all of A (4 images x 64 rows x 16 segs of 16B) ---
    {
        const unsigned short* srcs[4] = {g_Ah_hi, g_Ah_lo, g_Aa_hi, g_Aa_lo};
        const uint32_t dsts[4] = {OFF_AS, OFF_AS + A_IMG, OFF_AA, OFF_AA + A_IMG};
        #pragma unroll
        for (int it = 0; it < 16; it++) {
            int i = tid + it * 256;       // 0..4095
            int img = i >> 10;
            int rem = i & 1023;
            int r = rem >> 4;
            int seg = rem & 15;
            cp16(smb + (dsts[img] + r * RPA + seg * 4) * 4,
                 srcs[img] + (row0 + r) * D + seg * 8);
        }
    }
    // --- stage B chunk into buf ---
    auto stageB = [&](int ch, int buf) {
        #pragma unroll
        for (int it = 0; it < 4; it++) {
            int i = tid + it * 256;       // 0..1023
            int img = i >> 9;
            int rem = i & 511;
            int n = rem >> 2;
            int seg = rem & 3;
            cp16(smb + (OFF_B + buf * 2 * B_IMG + img * B_IMG + n * RPB + seg * 4) * 4,
                 &g_Bimg[layer][img][n][ch * 32 + seg * 8]);
        }
    };

    stageB(0, 0);
    CP_COMMIT();

    for (int ch = 0; ch < 8; ch++) {
        int buf = ch & 1;
        if (ch < 7) {
            stageB(ch + 1, buf ^ 1);
            CP_COMMIT();
            CP_WAIT(1);
        } else {
            CP_WAIT(0);
        }
        __syncthreads();

        const uint32_t* Ahi = sm + ((ch < 4) ? OFF_AS : OFF_AA);
        const uint32_t* Alo = Ahi + A_IMG;
        const uint32_t* B0 = sm + OFF_B + buf * 2 * B_IMG;
        const uint32_t* B1 = B0 + B_IMG;
        int chm = (ch & 3) * 16;          // word base within A row

        #pragma unroll
        for (int kk = 0; kk < 2; kk++) {
            uint32_t ah[2][4], al[2][4], bh[4][2], bl[4][2];
            #pragma unroll
            for (int mf = 0; mf < 2; mf++) {
                int wb = (wm * 32 + mf * 16 + g) * RPA + chm + kk * 8 + c;
                ah[mf][0] = Ahi[wb];
                ah[mf][1] = Ahi[wb + 8 * RPA];
                ah[mf][2] = Ahi[wb + 4];
                ah[mf][3] = Ahi[wb + 8 * RPA + 4];
                al[mf][0] = Alo[wb];
                al[mf][1] = Alo[wb + 8 * RPA];
                al[mf][2] = Alo[wb + 4];
                al[mf][3] = Alo[wb + 8 * RPA + 4];
            }
            #pragma unroll
            for (int nf = 0; nf < 4; nf++) {
                int wb = (wn * 32 + nf * 8 + g) * RPB + kk * 8 + c;
                bh[nf][0] = B0[wb];
                bh[nf][1] = B0[wb + 4];
                bl[nf][0] = B1[wb];
                bl[nf][1] = B1[wb + 4];
            }
            #pragma unroll
            for (int mf = 0; mf < 2; mf++)
                #pragma unroll
                for (int nf = 0; nf < 4; nf++) {
                    mma16816(acc[mf][nf], ah[mf], bh[nf]);
                    mma16816(acc[mf][nf], ah[mf], bl[nf]);
                    mma16816(acc[mf][nf], al[mf], bh[nf]);
                }
        }
        __syncthreads();
    }

    // --- epilogue: bias + relu, write fp32 out (+ next-layer self images) ---
    const float* bias_sm = (const float*)(sm + OFF_BIAS);
    #pragma unroll
    for (int mf = 0; mf < 2; mf++) {
        size_t r_lo = row0 + wm * 32 + mf * 16 + g;
        size_t r_hi = r_lo + 8;
        #pragma unroll
        for (int nf = 0; nf < 4; nf++) {
            int col = wn * 32 + nf * 8 + c * 2;
            float b0 = bias_sm[col], b1 = bias_sm[col + 1];
            float v00 = acc[mf][nf][0] + b0, v01 = acc[mf][nf][1] + b1;
            float v10 = acc[mf][nf][2] + b0, v11 = acc[mf][nf][3] + b1;
            if (do_relu) {
                v00 = fmaxf(v00, 0.f); v01 = fmaxf(v01, 0.f);
                v10 = fmaxf(v10, 0.f); v11 = fmaxf(v11, 0.f);
            }
            if (r_lo < N_NODES) {
                *(float2*)(out + r_lo * D + col) = make_float2(v00, v01);
                if (write_img) {
                    unsigned short h0, h1, l0, l1;
                    split_bf16(v00, h0, l0); split_bf16(v01, h1, l1);
                    *(uint32_t*)(g_Ah_hi + r_lo * D + col) = (uint32_t)h0 | ((uint32_t)h1 << 16);
                    *(uint32_t*)(g_Ah_lo + r_lo * D + col) = (uint32_t)l0 | ((uint32_t)l1 << 16);
                }
            }
            if (r_hi < N_NODES) {
                *(float2*)(out + r_hi * D + col) = make_float2(v10, v11);
                if (write_img) {
                    unsigned short h0, h1, l0, l1;
                    split_bf16(v10, h0, l0); split_bf16(v11, h1, l1);
                    *(uint32_t*)(g_Ah_hi + r_hi * D + col) = (uint32_t)h0 | ((uint32_t)h1 << 16);
                    *(uint32_t*)(g_Ah_lo + r_hi * D + col) = (uint32_t)l0 | ((uint32_t)l1 << 16);
                }
            }
        }
    }
}

// ---------------------------------------------------------------------------
// Launch
// ---------------------------------------------------------------------------
extern "C" void kernel_launch(void* const* d_in, const int* in_sizes, int n_in,
                              void* d_out, int out_size) {
    const float* x       = (const float*)d_in[0];
    const int*   src     = (const int*)d_in[1];
    const int*   dst     = (const int*)d_in[2];
    const float* w_self  = (const float*)d_in[3];
    const float* w_neigh = (const float*)d_in[4];
    const float* b       = (const float*)d_in[5];
    float*       out     = (float*)d_out;

    cudaFuncSetAttribute(mma_gemm_kernel, cudaFuncAttributeMaxDynamicSharedMemorySize,
                         SMEM_WORDS * 4);

    void* hptr_v = nullptr;
    cudaGetSymbolAddress(&hptr_v, g_h);
    float* hptr = (float*)hptr_v;

    // Prep: weight images + degree zero (merged) + CSR
    bprep_zero_kernel<<<384, 256>>>(w_self, w_neigh);
    count_kernel<<<N_EDGES / 256, 256>>>(dst);
    offsets_kernel<<<(N_NODES + 255) / 256, 256>>>();
    fill_kernel<<<N_EDGES / 256, 256>>>(src, dst);

    // Layer 0: agg(x) + convert x self images; gemm -> g_h + self images
    agg_kernel<<<N_NODES / 8, 256>>>(x, 1);
    mma_gemm_kernel<<<NTILES, 256, SMEM_WORDS * 4>>>(0, b, hptr, 1, 1);
    // Layer 1
    agg_kernel<<<N_NODES / 8, 256>>>(hptr, 0);
    mma_gemm_kernel<<<NTILES, 256, SMEM_WORDS * 4>>>(1, b + 128, hptr, 1, 1);
    // Layer 2: -> out, no relu, no images
    agg_kernel<<<N_NODES / 8, 256>>>(hptr, 0);
    mma_gemm_kernel<<<NTILES, 256, SMEM_WORDS * 4>>>(2, b + 256, out, 0, 0);
}